// round 5
// baseline (speedup 1.0000x reference)
#include <cuda_runtime.h>
#include <cuda_bf16.h>
#include <math.h>
#include <cstdint>

// Problem constants
#define Bsz 2
#define Tt 2048
#define Cc 1024
#define Hh 16
#define HD 64
#define NTOK (Bsz*Tt)   // 4096
#define C3 (3*Cc)       // 3072
#define KEEP_INV (1.0f/0.9f)

// ---------------- scratch (device globals; no allocs allowed) ---------------
__device__ __nv_bfloat16 g_xh[(size_t)NTOK*Cc],  g_xl[(size_t)NTOK*Cc];
__device__ __nv_bfloat16 g_wqh[(size_t)C3*Cc],   g_wql[(size_t)C3*Cc];   // [N,K]
__device__ __nv_bfloat16 g_wph[(size_t)Cc*Cc],   g_wpl[(size_t)Cc*Cc];   // [N,K]
__device__ __nv_bfloat16 g_yh[(size_t)NTOK*Cc],  g_yl[(size_t)NTOK*Cc];
// split q/k: [bh][t][64]; v transposed: [bh][d][t]
__device__ __nv_bfloat16 g_qh[(size_t)32*Tt*HD], g_ql[(size_t)32*Tt*HD];
__device__ __nv_bfloat16 g_kh[(size_t)32*Tt*HD], g_kl[(size_t)32*Tt*HD];
__device__ __nv_bfloat16 g_vth[(size_t)32*HD*Tt], g_vtl[(size_t)32*HD*Tt];

// ---------------- helpers ----------------
__device__ __forceinline__ uint32_t smem_u32(const void* p) {
    uint32_t a;
    asm("{ .reg .u64 t; cvta.to.shared.u64 t, %1; cvt.u32.u64 %0, t; }" : "=r"(a) : "l"(p));
    return a;
}
__device__ __forceinline__ void cp_async16(uint32_t dst, const void* src) {
    asm volatile("cp.async.cg.shared.global [%0], [%1], 16;" :: "r"(dst), "l"(src) : "memory");
}
#define CP_COMMIT() asm volatile("cp.async.commit_group;" ::: "memory")
#define CP_WAIT(n)  asm volatile("cp.async.wait_group %0;" :: "n"(n) : "memory")

__device__ __forceinline__ void mma16816(float* c, const uint32_t* a, const uint32_t* b) {
    asm volatile("mma.sync.aligned.m16n8k16.row.col.f32.bf16.bf16.f32 "
        "{%0,%1,%2,%3}, {%4,%5,%6,%7}, {%8,%9}, {%0,%1,%2,%3};"
        : "+f"(c[0]), "+f"(c[1]), "+f"(c[2]), "+f"(c[3])
        : "r"(a[0]), "r"(a[1]), "r"(a[2]), "r"(a[3]), "r"(b[0]), "r"(b[1]));
}
__device__ __forceinline__ void ldsm4(uint32_t* r, uint32_t a) {
    asm volatile("ldmatrix.sync.aligned.m8n8.x4.shared.b16 {%0,%1,%2,%3}, [%4];"
        : "=r"(r[0]), "=r"(r[1]), "=r"(r[2]), "=r"(r[3]) : "r"(a));
}
// pack two floats into hi/lo bf16x2 (split)
__device__ __forceinline__ void split2(float a, float b, uint32_t& hi, uint32_t& lo) {
    __nv_bfloat16 ha = __float2bfloat16(a), hb = __float2bfloat16(b);
    __nv_bfloat162 H(ha, hb);
    hi = *(uint32_t*)&H;
    __nv_bfloat162 L(__float2bfloat16(a - __bfloat162float(ha)),
                     __float2bfloat16(b - __bfloat162float(hb)));
    lo = *(uint32_t*)&L;
}

// ---------------------------------------------------------------------------
// fp32 -> (hi,lo) bf16 split
// ---------------------------------------------------------------------------
__global__ __launch_bounds__(256) void cvt_split(const float4* __restrict__ in,
                                                 __nv_bfloat162* __restrict__ hi,
                                                 __nv_bfloat162* __restrict__ lo,
                                                 int n4) {
    int i = blockIdx.x * 256 + threadIdx.x;
    if (i >= n4) return;
    float4 v = in[i];
    __nv_bfloat16 hx = __float2bfloat16(v.x), hy = __float2bfloat16(v.y);
    __nv_bfloat16 hz = __float2bfloat16(v.z), hw = __float2bfloat16(v.w);
    hi[2*i]   = __nv_bfloat162(hx, hy);
    hi[2*i+1] = __nv_bfloat162(hz, hw);
    lo[2*i]   = __nv_bfloat162(__float2bfloat16(v.x - __bfloat162float(hx)),
                               __float2bfloat16(v.y - __bfloat162float(hy)));
    lo[2*i+1] = __nv_bfloat162(__float2bfloat16(v.z - __bfloat162float(hz)),
                               __float2bfloat16(v.w - __bfloat162float(hw)));
}

// fp32 W[K,N] -> transposed split bf16 [N,K]
__global__ __launch_bounds__(256) void cvt_split_T(const float* __restrict__ in,
                                                   __nv_bfloat16* __restrict__ hi,
                                                   __nv_bfloat16* __restrict__ lo,
                                                   int K, int N) {
    __shared__ float t[32][33];
    int nx = blockIdx.x * 32, kx = blockIdx.y * 32;
    int tx = threadIdx.x, ty = threadIdx.y;  // (32,8)
    #pragma unroll
    for (int r = 0; r < 4; ++r)
        t[ty + 8*r][tx] = in[(size_t)(kx + ty + 8*r) * N + nx + tx];
    __syncthreads();
    #pragma unroll
    for (int r = 0; r < 4; ++r) {
        float v = t[tx][ty + 8*r];
        size_t o = (size_t)(nx + ty + 8*r) * K + kx + tx;
        __nv_bfloat16 h = __float2bfloat16(v);
        hi[o] = h;
        lo[o] = __float2bfloat16(v - __bfloat162float(h));
    }
}

// ---------------------------------------------------------------------------
// mma.sync split-bf16 GEMM: C[M,N] = A[M,K]*B[N,K]^T (+bias, +epilogue)
// 128x128 block tile, K-chunk 32, 8 warps (4x2) of 32x64, 3-stage cp.async,
// ldmatrix.x4 fragment loads.
// MODE 0: qkv -> split q/k ([bh][t][64], q scaled 1/8) and transposed split v.
// MODE 1: proj + resid dropout -> out (fp32).
// ---------------------------------------------------------------------------
#define SR 40
#define TILE_E (128*SR)         // elems per array tile
#define TILE_B (TILE_E*2)       // 10240 bytes
#define BUF_E  (4*TILE_E)
#define BUF_B  (4*TILE_B)       // 40960 bytes
#define GEMM_SMEM (3*BUF_B)     // 122880

__device__ __forceinline__ void gemm_issue(uint32_t sb, int buf,
                                           const __nv_bfloat16* Ah, const __nv_bfloat16* Al,
                                           const __nv_bfloat16* Bh, const __nv_bfloat16* Bl,
                                           int m0, int n0, int K, int ch, int tid) {
    #pragma unroll
    for (int it = 0; it < 8; ++it) {
        int u = tid + it * 256;
        int arr = u >> 9;
        int rem = u & 511;
        int row = rem >> 2;
        int c16 = rem & 3;
        const __nv_bfloat16* src = (arr == 0) ? Ah : (arr == 1) ? Al : (arr == 2) ? Bh : Bl;
        int grow = (arr < 2 ? m0 : n0) + row;
        uint32_t soff = (uint32_t)((buf * BUF_E + arr * TILE_E + row * SR + c16 * 8) * 2);
        cp_async16(sb + soff, src + (size_t)grow * K + ch * 32 + c16 * 8);
    }
    CP_COMMIT();
}

template<int MODE>
__global__ __launch_bounds__(256) void gemm_mma(const __nv_bfloat16* __restrict__ Ah,
                                                const __nv_bfloat16* __restrict__ Al,
                                                const __nv_bfloat16* __restrict__ Bh,
                                                const __nv_bfloat16* __restrict__ Bl,
                                                const float* __restrict__ bias,
                                                const unsigned* __restrict__ rmask,
                                                float* __restrict__ out,
                                                int K) {
    extern __shared__ __nv_bfloat16 smg[];
    uint32_t sb = smem_u32(smg);
    int tid = threadIdx.x, wid = tid >> 5, lane = tid & 31;
    int m0 = blockIdx.y * 128, n0 = blockIdx.x * 128;
    int wm = (wid & 3) * 32, wn = (wid >> 2) * 64;
    int qr = lane >> 2, qc = lane & 3;
    int g = lane >> 3, lr = lane & 7;

    // ldmatrix byte offsets within an array tile
    uint32_t aoff[2], boff[4];
    #pragma unroll
    for (int i = 0; i < 2; ++i)
        aoff[i] = (uint32_t)(((wm + i*16 + lr + (g & 1)*8) * SR + (g >> 1)*8) * 2);
    #pragma unroll
    for (int jp = 0; jp < 4; ++jp)
        boff[jp] = (uint32_t)(((wn + jp*16 + lr + (g >> 1)*8) * SR + (g & 1)*8) * 2);

    float acc[2][8][4] = {};
    int nch = K >> 5;

    gemm_issue(sb, 0, Ah, Al, Bh, Bl, m0, n0, K, 0, tid);
    gemm_issue(sb, 1, Ah, Al, Bh, Bl, m0, n0, K, 1, tid);

    int buf = 0;
    for (int ch = 0; ch < nch; ++ch) {
        if (ch + 2 < nch) {
            int nb = buf + 2; if (nb >= 3) nb -= 3;
            gemm_issue(sb, nb, Ah, Al, Bh, Bl, m0, n0, K, ch + 2, tid);
            CP_WAIT(2);
        } else if (ch + 1 < nch) {
            CP_WAIT(1);
        } else {
            CP_WAIT(0);
        }
        __syncthreads();

        uint32_t bAh = sb + buf * BUF_B;
        uint32_t bAl = bAh + TILE_B;
        uint32_t bBh = bAh + 2*TILE_B;
        uint32_t bBl = bAh + 3*TILE_B;

        #pragma unroll
        for (int ks = 0; ks < 2; ++ks) {
            uint32_t ksb = ks * 32;          // 16 bf16 = 32 bytes
            uint32_t ah[2][4], al[2][4];
            ldsm4(ah[0], bAh + aoff[0] + ksb);
            ldsm4(ah[1], bAh + aoff[1] + ksb);
            ldsm4(al[0], bAl + aoff[0] + ksb);
            ldsm4(al[1], bAl + aoff[1] + ksb);
            #pragma unroll
            for (int jp = 0; jp < 4; ++jp) {
                uint32_t bh4[4], bl4[4];
                ldsm4(bh4, bBh + boff[jp] + ksb);
                ldsm4(bl4, bBl + boff[jp] + ksb);
                #pragma unroll
                for (int jj = 0; jj < 2; ++jj) {
                    int j = jp*2 + jj;
                    #pragma unroll
                    for (int i = 0; i < 2; ++i) {
                        mma16816(acc[i][j], ah[i], bh4 + jj*2);
                        mma16816(acc[i][j], ah[i], bl4 + jj*2);
                        mma16816(acc[i][j], al[i], bh4 + jj*2);
                    }
                }
            }
        }
        __syncthreads();
        if (++buf == 3) buf = 0;
    }

    // Epilogue
    #pragma unroll
    for (int i = 0; i < 2; ++i) {
        int R0 = m0 + wm + i * 16 + qr;
        #pragma unroll
        for (int j = 0; j < 8; ++j) {
            int C0 = n0 + wn + j * 8 + qc * 2;
            float b0 = bias[C0], b1 = bias[C0 + 1];
            #pragma unroll
            for (int hrow = 0; hrow < 2; ++hrow) {
                int m = R0 + hrow * 8;
                float v0 = acc[i][j][hrow*2 + 0] + b0;
                float v1 = acc[i][j][hrow*2 + 1] + b1;
                if (MODE == 0) {
                    int bb = m >> 11, t = m & (Tt - 1);
                    int which = C0 >> 10, cidx = C0 & 1023;
                    int h = cidx >> 6, dd = cidx & 63;
                    int bh = bb * Hh + h;
                    if (which == 0) { v0 *= 0.125f; v1 *= 0.125f; }
                    uint32_t hi, lo;
                    split2(v0, v1, hi, lo);
                    if (which == 2) {
                        size_t o0 = ((size_t)bh*HD + dd)*Tt + t;
                        size_t o1 = ((size_t)bh*HD + dd + 1)*Tt + t;
                        __nv_bfloat162 H = *(__nv_bfloat162*)&hi;
                        __nv_bfloat162 L = *(__nv_bfloat162*)&lo;
                        g_vth[o0] = H.x; g_vth[o1] = H.y;
                        g_vtl[o0] = L.x; g_vtl[o1] = L.y;
                    } else {
                        size_t o = ((size_t)bh*Tt + t)*HD + dd;
                        __nv_bfloat16* dh = (which == 0) ? g_qh : g_kh;
                        __nv_bfloat16* dl = (which == 0) ? g_ql : g_kl;
                        *(uint32_t*)&dh[o] = hi;
                        *(uint32_t*)&dl[o] = lo;
                    }
                } else {
                    size_t idx = (size_t)m * Cc + C0;
                    out[idx]     = rmask[idx]     ? v0 * KEEP_INV : 0.f;
                    out[idx + 1] = rmask[idx + 1] ? v1 * KEEP_INV : 0.f;
                }
            }
        }
    }
}

// ---------------------------------------------------------------------------
// Flash attention on HMMA + ldmatrix: 128 q-rows per CTA, 64-wide k-tiles.
// ---------------------------------------------------------------------------
#define SRK 72                       // bf16 row stride for 64-col tiles
#define SRM 68                       // uint row stride for mask tile
#define OQH 0
#define OQL (128*SRK*2)              // 18432
#define OB0 (2*128*SRK*2)            // 36864
#define KVB (64*SRK*2)               // 9216
#define OMK (4*KVB)
#define BUFB (4*KVB + 128*SRM*4)     // 71680
#define FLASH_SMEM (OB0 + 2*BUFB)    // 180224

__device__ __forceinline__ void flash_issue(uint32_t sb, int buf,
                                            int bh, int q0, int k0,
                                            const unsigned* amask, int tid) {
    #pragma unroll
    for (int it = 0; it < 8; ++it) {
        int u = tid + it * 256;
        int arr = u >> 9;
        int rem = u & 511;
        int row = rem >> 3;
        int ck = rem & 7;
        const __nv_bfloat16* src;
        size_t gofs;
        if (arr < 2) {
            src = (arr == 0) ? g_kh : g_kl;
            gofs = ((size_t)bh*Tt + k0 + row)*HD + ck*8;
        } else {
            src = (arr == 2) ? g_vth : g_vtl;
            gofs = ((size_t)bh*HD + row)*Tt + k0 + ck*8;
        }
        uint32_t dst = sb + OB0 + buf*BUFB + arr*KVB + (uint32_t)(row*SRK + ck*8)*2;
        cp_async16(dst, src + gofs);
    }
    #pragma unroll
    for (int it = 0; it < 8; ++it) {
        int u = tid + it * 256;
        int row = u >> 4;
        int cu = u & 15;
        const unsigned* src = amask + ((size_t)bh*Tt + q0 + row)*Tt + k0 + cu*4;
        uint32_t dst = sb + OB0 + buf*BUFB + OMK + (uint32_t)(row*SRM*4 + cu*16);
        cp_async16(dst, src);
    }
    CP_COMMIT();
}

__global__ __launch_bounds__(256) void flash_mma(const unsigned* __restrict__ amask) {
    extern __shared__ char smf[];
    uint32_t sb = smem_u32(smf);
    int tid = threadIdx.x, wid = tid >> 5, lane = tid & 31;
    int qr = lane >> 2, qc = lane & 3;
    int g = lane >> 3, lr = lane & 7;
    int bh = blockIdx.y;
    int qb = (gridDim.x - 1) - blockIdx.x;   // big tiles first
    int q0 = qb * 128;
    int nkt = qb * 2 + 2;

    // Q tile load (split) — same cp.async group as tile 0
    #pragma unroll
    for (int it = 0; it < 8; ++it) {
        int u = tid + it * 256;
        int arr = u >> 10;
        int rem = u & 1023;
        int row = rem >> 3;
        int ck = rem & 7;
        const __nv_bfloat16* src = arr ? g_ql : g_qh;
        uint32_t dst = sb + (arr ? OQL : OQH) + (uint32_t)(row*SRK + ck*8)*2;
        cp_async16(dst, src + ((size_t)bh*Tt + q0 + row)*HD + ck*8);
    }
    flash_issue(sb, 0, bh, q0, 0, amask, tid);

    // ldmatrix offsets
    uint32_t qaoff = (uint32_t)(((wid*16 + lr + (g & 1)*8) * SRK + (g >> 1)*8) * 2);
    uint32_t bofff[4];
    #pragma unroll
    for (int jp = 0; jp < 4; ++jp)
        bofff[jp] = (uint32_t)(((jp*16 + lr + (g >> 1)*8) * SRK + (g & 1)*8) * 2);

    int r = wid * 16 + qr;                  // q row within tile
    int rowmax = q0 + wid * 16 + 15;
    float acc[8][4] = {};
    float m0 = -INFINITY, m1 = -INFINITY, l0 = 0.f, l1 = 0.f;

    for (int kt = 0; kt < nkt; ++kt) {
        int buf = kt & 1;
        int k0 = kt * 64;
        if (kt + 1 < nkt) {
            flash_issue(sb, buf ^ 1, bh, q0, (kt+1)*64, amask, tid);
            CP_WAIT(1);
        } else {
            CP_WAIT(0);
        }
        __syncthreads();

        if (k0 <= rowmax) {
            uint32_t kbh = sb + OB0 + buf*BUFB;
            uint32_t kbl = kbh + KVB;
            uint32_t vbh = kbh + 2*KVB;
            uint32_t vbl = kbh + 3*KVB;
            const unsigned* pMk = (const unsigned*)(smf + OB0 + buf*BUFB + OMK);

            // ---- S = Q K^T (split 3-term) ----
            float s[8][4] = {};
            #pragma unroll
            for (int ks = 0; ks < 4; ++ks) {
                uint32_t ksb = ks * 32;
                uint32_t ah[4], al[4];
                ldsm4(ah, sb + OQH + qaoff + ksb);
                ldsm4(al, sb + OQL + qaoff + ksb);
                #pragma unroll
                for (int jp = 0; jp < 4; ++jp) {
                    uint32_t kh4[4], kl4[4];
                    ldsm4(kh4, kbh + bofff[jp] + ksb);
                    ldsm4(kl4, kbl + bofff[jp] + ksb);
                    #pragma unroll
                    for (int jj = 0; jj < 2; ++jj) {
                        mma16816(s[jp*2+jj], ah, kh4 + jj*2);
                        mma16816(s[jp*2+jj], ah, kl4 + jj*2);
                        mma16816(s[jp*2+jj], al, kh4 + jj*2);
                    }
                }
            }

            // ---- causal mask ----
            int row0 = q0 + r, row1 = row0 + 8;
            #pragma unroll
            for (int j = 0; j < 8; ++j) {
                int cg = k0 + j*8 + qc*2;
                if (cg     > row0) s[j][0] = -INFINITY;
                if (cg + 1 > row0) s[j][1] = -INFINITY;
                if (cg     > row1) s[j][2] = -INFINITY;
                if (cg + 1 > row1) s[j][3] = -INFINITY;
            }

            // ---- online softmax (undropped denominator) ----
            float mx0 = -INFINITY, mx1 = -INFINITY;
            #pragma unroll
            for (int j = 0; j < 8; ++j) {
                mx0 = fmaxf(mx0, fmaxf(s[j][0], s[j][1]));
                mx1 = fmaxf(mx1, fmaxf(s[j][2], s[j][3]));
            }
            mx0 = fmaxf(mx0, __shfl_xor_sync(0xffffffffu, mx0, 1));
            mx0 = fmaxf(mx0, __shfl_xor_sync(0xffffffffu, mx0, 2));
            mx1 = fmaxf(mx1, __shfl_xor_sync(0xffffffffu, mx1, 1));
            mx1 = fmaxf(mx1, __shfl_xor_sync(0xffffffffu, mx1, 2));
            float m0n = fmaxf(m0, mx0), m1n = fmaxf(m1, mx1);
            float a0 = __expf(m0 - m0n), a1 = __expf(m1 - m1n);
            float sum0 = 0.f, sum1 = 0.f;
            int mr0 = (wid*16 + qr) * SRM;
            int mr1 = mr0 + 8*SRM;
            #pragma unroll
            for (int j = 0; j < 8; ++j) {
                uint2 k0m = *(const uint2*)&pMk[mr0 + j*8 + qc*2];
                uint2 k1m = *(const uint2*)&pMk[mr1 + j*8 + qc*2];
                float p0 = __expf(s[j][0] - m0n); sum0 += p0;
                float p1 = __expf(s[j][1] - m0n); sum0 += p1;
                float p2 = __expf(s[j][2] - m1n); sum1 += p2;
                float p3 = __expf(s[j][3] - m1n); sum1 += p3;
                s[j][0] = k0m.x ? p0 * KEEP_INV : 0.f;
                s[j][1] = k0m.y ? p1 * KEEP_INV : 0.f;
                s[j][2] = k1m.x ? p2 * KEEP_INV : 0.f;
                s[j][3] = k1m.y ? p3 * KEEP_INV : 0.f;
            }
            sum0 += __shfl_xor_sync(0xffffffffu, sum0, 1);
            sum0 += __shfl_xor_sync(0xffffffffu, sum0, 2);
            sum1 += __shfl_xor_sync(0xffffffffu, sum1, 1);
            sum1 += __shfl_xor_sync(0xffffffffu, sum1, 2);
            l0 = l0 * a0 + sum0;
            l1 = l1 * a1 + sum1;
            m0 = m0n; m1 = m1n;

            // ---- acc scale + P V (split 3-term, P from registers) ----
            #pragma unroll
            for (int j = 0; j < 8; ++j) {
                acc[j][0] *= a0; acc[j][1] *= a0;
                acc[j][2] *= a1; acc[j][3] *= a1;
            }
            #pragma unroll
            for (int s4 = 0; s4 < 4; ++s4) {
                uint32_t ph[4], pl[4];
                split2(s[2*s4][0],   s[2*s4][1],   ph[0], pl[0]);
                split2(s[2*s4][2],   s[2*s4][3],   ph[1], pl[1]);
                split2(s[2*s4+1][0], s[2*s4+1][1], ph[2], pl[2]);
                split2(s[2*s4+1][2], s[2*s4+1][3], ph[3], pl[3]);
                uint32_t ksb = s4 * 32;
                #pragma unroll
                for (int jp = 0; jp < 4; ++jp) {
                    uint32_t vh4[4], vl4[4];
                    ldsm4(vh4, vbh + bofff[jp] + ksb);
                    ldsm4(vl4, vbl + bofff[jp] + ksb);
                    #pragma unroll
                    for (int jj = 0; jj < 2; ++jj) {
                        mma16816(acc[jp*2+jj], ph, vh4 + jj*2);
                        mma16816(acc[jp*2+jj], ph, vl4 + jj*2);
                        mma16816(acc[jp*2+jj], pl, vh4 + jj*2);
                    }
                }
            }
        }
        __syncthreads();
    }

    // ---- epilogue: y = acc / l, write split bf16 [tok][C] ----
    int b = bh >> 4, h = bh & 15;
    float inv0 = 1.f / l0, inv1 = 1.f / l1;
    size_t tok0 = (size_t)b*Tt + q0 + r;
    size_t tok1 = tok0 + 8;
    #pragma unroll
    for (int j = 0; j < 8; ++j) {
        int col = h*HD + j*8 + qc*2;
        uint32_t hi, lo;
        split2(acc[j][0]*inv0, acc[j][1]*inv0, hi, lo);
        *(uint32_t*)&g_yh[tok0*Cc + col] = hi;
        *(uint32_t*)&g_yl[tok0*Cc + col] = lo;
        split2(acc[j][2]*inv1, acc[j][3]*inv1, hi, lo);
        *(uint32_t*)&g_yh[tok1*Cc + col] = hi;
        *(uint32_t*)&g_yl[tok1*Cc + col] = lo;
    }
}

// ---------------------------------------------------------------------------
extern "C" void kernel_launch(void* const* d_in, const int* in_sizes, int n_in,
                              void* d_out, int out_size) {
    const float* x     = (const float*)d_in[0];
    const float* Wqkv  = (const float*)d_in[1];
    const float* bqkv  = (const float*)d_in[2];
    const float* Wproj = (const float*)d_in[3];
    const float* bproj = (const float*)d_in[4];
    const unsigned* amask = (const unsigned*)d_in[5];
    const unsigned* rmask = (const unsigned*)d_in[6];
    float* out = (float*)d_out;

    cudaFuncSetAttribute(gemm_mma<0>, cudaFuncAttributeMaxDynamicSharedMemorySize, GEMM_SMEM);
    cudaFuncSetAttribute(gemm_mma<1>, cudaFuncAttributeMaxDynamicSharedMemorySize, GEMM_SMEM);
    cudaFuncSetAttribute(flash_mma, cudaFuncAttributeMaxDynamicSharedMemorySize, FLASH_SMEM);

    __nv_bfloat16 *xh, *xl, *wqh, *wql, *wph, *wpl, *yh, *yl;
    cudaGetSymbolAddress((void**)&xh,  g_xh);  cudaGetSymbolAddress((void**)&xl,  g_xl);
    cudaGetSymbolAddress((void**)&wqh, g_wqh); cudaGetSymbolAddress((void**)&wql, g_wql);
    cudaGetSymbolAddress((void**)&wph, g_wph); cudaGetSymbolAddress((void**)&wpl, g_wpl);
    cudaGetSymbolAddress((void**)&yh,  g_yh);  cudaGetSymbolAddress((void**)&yl,  g_yl);

    cvt_split<<<(NTOK*Cc/4 + 255)/256, 256>>>((const float4*)x, (__nv_bfloat162*)xh, (__nv_bfloat162*)xl, NTOK*Cc/4);
    cvt_split_T<<<dim3(C3/32, Cc/32), dim3(32,8)>>>(Wqkv, wqh, wql, Cc, C3);
    cvt_split_T<<<dim3(Cc/32, Cc/32), dim3(32,8)>>>(Wproj, wph, wpl, Cc, Cc);

    gemm_mma<0><<<dim3(C3/128, NTOK/128), 256, GEMM_SMEM>>>(xh, xl, wqh, wql, bqkv, nullptr, nullptr, Cc);

    flash_mma<<<dim3(Tt/128, Bsz*Hh), 256, FLASH_SMEM>>>(amask);

    gemm_mma<1><<<dim3(Cc/128, NTOK/128), 256, GEMM_SMEM>>>(yh, yl, wph, wpl, bproj, rmask, out, Cc);
}

// round 6
// speedup vs baseline: 1.0969x; 1.0969x over previous
#include <cuda_runtime.h>
#include <cuda_bf16.h>
#include <math.h>
#include <cstdint>

// Problem constants
#define Bsz 2
#define Tt 2048
#define Cc 1024
#define Hh 16
#define HD 64
#define NTOK (Bsz*Tt)   // 4096
#define C3 (3*Cc)       // 3072
#define KEEP_INV (1.0f/0.9f)

// ---------------- scratch (device globals; no allocs allowed) ---------------
__device__ __nv_bfloat16 g_xh[(size_t)NTOK*Cc],  g_xl[(size_t)NTOK*Cc];
__device__ __nv_bfloat16 g_wqh[(size_t)C3*Cc],   g_wql[(size_t)C3*Cc];   // [N,K]
__device__ __nv_bfloat16 g_wph[(size_t)Cc*Cc],   g_wpl[(size_t)Cc*Cc];   // [N,K]
__device__ __nv_bfloat16 g_yh[(size_t)NTOK*Cc],  g_yl[(size_t)NTOK*Cc];
// split q/k: [bh][t][64]; v transposed: [bh][d][t]
__device__ __nv_bfloat16 g_qh[(size_t)32*Tt*HD], g_ql[(size_t)32*Tt*HD];
__device__ __nv_bfloat16 g_kh[(size_t)32*Tt*HD], g_kl[(size_t)32*Tt*HD];
__device__ __nv_bfloat16 g_vth[(size_t)32*HD*Tt], g_vtl[(size_t)32*HD*Tt];

// ---------------- helpers ----------------
__device__ __forceinline__ uint32_t smem_u32(const void* p) {
    uint32_t a;
    asm("{ .reg .u64 t; cvta.to.shared.u64 t, %1; cvt.u32.u64 %0, t; }" : "=r"(a) : "l"(p));
    return a;
}
__device__ __forceinline__ void cp_async16(uint32_t dst, const void* src) {
    asm volatile("cp.async.cg.shared.global [%0], [%1], 16;" :: "r"(dst), "l"(src) : "memory");
}
#define CP_COMMIT() asm volatile("cp.async.commit_group;" ::: "memory")
#define CP_WAIT(n)  asm volatile("cp.async.wait_group %0;" :: "n"(n) : "memory")

__device__ __forceinline__ void mma16816(float* c, const uint32_t* a, const uint32_t* b) {
    asm volatile("mma.sync.aligned.m16n8k16.row.col.f32.bf16.bf16.f32 "
        "{%0,%1,%2,%3}, {%4,%5,%6,%7}, {%8,%9}, {%0,%1,%2,%3};"
        : "+f"(c[0]), "+f"(c[1]), "+f"(c[2]), "+f"(c[3])
        : "r"(a[0]), "r"(a[1]), "r"(a[2]), "r"(a[3]), "r"(b[0]), "r"(b[1]));
}
__device__ __forceinline__ void ldsm4(uint32_t* r, uint32_t a) {
    asm volatile("ldmatrix.sync.aligned.m8n8.x4.shared.b16 {%0,%1,%2,%3}, [%4];"
        : "=r"(r[0]), "=r"(r[1]), "=r"(r[2]), "=r"(r[3]) : "r"(a));
}
// pack two floats into hi/lo bf16x2 (split)
__device__ __forceinline__ void split2(float a, float b, uint32_t& hi, uint32_t& lo) {
    __nv_bfloat16 ha = __float2bfloat16(a), hb = __float2bfloat16(b);
    __nv_bfloat162 H(ha, hb);
    hi = *(uint32_t*)&H;
    __nv_bfloat162 L(__float2bfloat16(a - __bfloat162float(ha)),
                     __float2bfloat16(b - __bfloat162float(hb)));
    lo = *(uint32_t*)&L;
}

// ---------------------------------------------------------------------------
// fp32 -> (hi,lo) bf16 split
// ---------------------------------------------------------------------------
__global__ __launch_bounds__(256) void cvt_split(const float4* __restrict__ in,
                                                 __nv_bfloat162* __restrict__ hi,
                                                 __nv_bfloat162* __restrict__ lo,
                                                 int n4) {
    int i = blockIdx.x * 256 + threadIdx.x;
    if (i >= n4) return;
    float4 v = in[i];
    __nv_bfloat16 hx = __float2bfloat16(v.x), hy = __float2bfloat16(v.y);
    __nv_bfloat16 hz = __float2bfloat16(v.z), hw = __float2bfloat16(v.w);
    hi[2*i]   = __nv_bfloat162(hx, hy);
    hi[2*i+1] = __nv_bfloat162(hz, hw);
    lo[2*i]   = __nv_bfloat162(__float2bfloat16(v.x - __bfloat162float(hx)),
                               __float2bfloat16(v.y - __bfloat162float(hy)));
    lo[2*i+1] = __nv_bfloat162(__float2bfloat16(v.z - __bfloat162float(hz)),
                               __float2bfloat16(v.w - __bfloat162float(hw)));
}

// fp32 W[K,N] -> transposed split bf16 [N,K]
__global__ __launch_bounds__(256) void cvt_split_T(const float* __restrict__ in,
                                                   __nv_bfloat16* __restrict__ hi,
                                                   __nv_bfloat16* __restrict__ lo,
                                                   int K, int N) {
    __shared__ float t[32][33];
    int nx = blockIdx.x * 32, kx = blockIdx.y * 32;
    int tx = threadIdx.x, ty = threadIdx.y;  // (32,8)
    #pragma unroll
    for (int r = 0; r < 4; ++r)
        t[ty + 8*r][tx] = in[(size_t)(kx + ty + 8*r) * N + nx + tx];
    __syncthreads();
    #pragma unroll
    for (int r = 0; r < 4; ++r) {
        float v = t[tx][ty + 8*r];
        size_t o = (size_t)(nx + ty + 8*r) * K + kx + tx;
        __nv_bfloat16 h = __float2bfloat16(v);
        hi[o] = h;
        lo[o] = __float2bfloat16(v - __bfloat162float(h));
    }
}

// ---------------------------------------------------------------------------
// mma.sync split-bf16 GEMM: 128x128 tile, K-chunk 32, 2-stage cp.async,
// ldmatrix.x4 fragment loads. 80KB smem -> 2 CTAs/SM.
// ---------------------------------------------------------------------------
#define SR 40
#define TILE_E (128*SR)
#define TILE_B (TILE_E*2)       // 10240 bytes
#define BUF_E  (4*TILE_E)
#define BUF_B  (4*TILE_B)       // 40960 bytes
#define GEMM_SMEM (2*BUF_B)     // 81920

__device__ __forceinline__ void gemm_issue(uint32_t sb, int buf,
                                           const __nv_bfloat16* Ah, const __nv_bfloat16* Al,
                                           const __nv_bfloat16* Bh, const __nv_bfloat16* Bl,
                                           int m0, int n0, int K, int ch, int tid) {
    #pragma unroll
    for (int it = 0; it < 8; ++it) {
        int u = tid + it * 256;
        int arr = u >> 9;
        int rem = u & 511;
        int row = rem >> 2;
        int c16 = rem & 3;
        const __nv_bfloat16* src = (arr == 0) ? Ah : (arr == 1) ? Al : (arr == 2) ? Bh : Bl;
        int grow = (arr < 2 ? m0 : n0) + row;
        uint32_t soff = (uint32_t)((buf * BUF_E + arr * TILE_E + row * SR + c16 * 8) * 2);
        cp_async16(sb + soff, src + (size_t)grow * K + ch * 32 + c16 * 8);
    }
    CP_COMMIT();
}

template<int MODE>
__global__ __launch_bounds__(256, 2) void gemm_mma(const __nv_bfloat16* __restrict__ Ah,
                                                   const __nv_bfloat16* __restrict__ Al,
                                                   const __nv_bfloat16* __restrict__ Bh,
                                                   const __nv_bfloat16* __restrict__ Bl,
                                                   const float* __restrict__ bias,
                                                   const unsigned* __restrict__ rmask,
                                                   float* __restrict__ out,
                                                   int K) {
    extern __shared__ __nv_bfloat16 smg[];
    uint32_t sb = smem_u32(smg);
    int tid = threadIdx.x, wid = tid >> 5, lane = tid & 31;
    int m0 = blockIdx.y * 128, n0 = blockIdx.x * 128;
    int wm = (wid & 3) * 32, wn = (wid >> 2) * 64;
    int qr = lane >> 2, qc = lane & 3;
    int g = lane >> 3, lr = lane & 7;

    uint32_t aoff[2], boff[4];
    #pragma unroll
    for (int i = 0; i < 2; ++i)
        aoff[i] = (uint32_t)(((wm + i*16 + lr + (g & 1)*8) * SR + (g >> 1)*8) * 2);
    #pragma unroll
    for (int jp = 0; jp < 4; ++jp)
        boff[jp] = (uint32_t)(((wn + jp*16 + lr + (g >> 1)*8) * SR + (g & 1)*8) * 2);

    float acc[2][8][4] = {};
    int nch = K >> 5;

    gemm_issue(sb, 0, Ah, Al, Bh, Bl, m0, n0, K, 0, tid);

    for (int ch = 0; ch < nch; ++ch) {
        int buf = ch & 1;
        if (ch + 1 < nch) {
            gemm_issue(sb, buf ^ 1, Ah, Al, Bh, Bl, m0, n0, K, ch + 1, tid);
            CP_WAIT(1);
        } else {
            CP_WAIT(0);
        }
        __syncthreads();

        uint32_t bAh = sb + buf * BUF_B;
        uint32_t bAl = bAh + TILE_B;
        uint32_t bBh = bAh + 2*TILE_B;
        uint32_t bBl = bAh + 3*TILE_B;

        #pragma unroll
        for (int ks = 0; ks < 2; ++ks) {
            uint32_t ksb = ks * 32;
            uint32_t ah[2][4], al[2][4];
            ldsm4(ah[0], bAh + aoff[0] + ksb);
            ldsm4(ah[1], bAh + aoff[1] + ksb);
            ldsm4(al[0], bAl + aoff[0] + ksb);
            ldsm4(al[1], bAl + aoff[1] + ksb);
            #pragma unroll
            for (int jp = 0; jp < 4; ++jp) {
                uint32_t bh4[4], bl4[4];
                ldsm4(bh4, bBh + boff[jp] + ksb);
                ldsm4(bl4, bBl + boff[jp] + ksb);
                #pragma unroll
                for (int jj = 0; jj < 2; ++jj) {
                    int j = jp*2 + jj;
                    #pragma unroll
                    for (int i = 0; i < 2; ++i) {
                        mma16816(acc[i][j], ah[i], bh4 + jj*2);
                        mma16816(acc[i][j], ah[i], bl4 + jj*2);
                        mma16816(acc[i][j], al[i], bh4 + jj*2);
                    }
                }
            }
        }
        __syncthreads();
    }

    // Epilogue
    #pragma unroll
    for (int i = 0; i < 2; ++i) {
        int R0 = m0 + wm + i * 16 + qr;
        #pragma unroll
        for (int j = 0; j < 8; ++j) {
            int C0 = n0 + wn + j * 8 + qc * 2;
            float b0 = bias[C0], b1 = bias[C0 + 1];
            #pragma unroll
            for (int hrow = 0; hrow < 2; ++hrow) {
                int m = R0 + hrow * 8;
                float v0 = acc[i][j][hrow*2 + 0] + b0;
                float v1 = acc[i][j][hrow*2 + 1] + b1;
                if (MODE == 0) {
                    int bb = m >> 11, t = m & (Tt - 1);
                    int which = C0 >> 10, cidx = C0 & 1023;
                    int h = cidx >> 6, dd = cidx & 63;
                    int bh = bb * Hh + h;
                    if (which == 0) { v0 *= 0.125f; v1 *= 0.125f; }
                    uint32_t hi, lo;
                    split2(v0, v1, hi, lo);
                    if (which == 2) {
                        size_t o0 = ((size_t)bh*HD + dd)*Tt + t;
                        size_t o1 = ((size_t)bh*HD + dd + 1)*Tt + t;
                        __nv_bfloat162 H = *(__nv_bfloat162*)&hi;
                        __nv_bfloat162 L = *(__nv_bfloat162*)&lo;
                        g_vth[o0] = H.x; g_vth[o1] = H.y;
                        g_vtl[o0] = L.x; g_vtl[o1] = L.y;
                    } else {
                        size_t o = ((size_t)bh*Tt + t)*HD + dd;
                        __nv_bfloat16* dh = (which == 0) ? g_qh : g_kh;
                        __nv_bfloat16* dl = (which == 0) ? g_ql : g_kl;
                        *(uint32_t*)&dh[o] = hi;
                        *(uint32_t*)&dl[o] = lo;
                    }
                } else {
                    size_t idx = (size_t)m * Cc + C0;
                    out[idx]     = rmask[idx]     ? v0 * KEEP_INV : 0.f;
                    out[idx + 1] = rmask[idx + 1] ? v1 * KEEP_INV : 0.f;
                }
            }
        }
    }
}

// ---------------------------------------------------------------------------
// Flash attention on HMMA + ldmatrix. Mask read direct from gmem (prefetched
// into registers behind the QK MMAs). 108KB smem -> 2 CTAs/SM.
// ---------------------------------------------------------------------------
#define SRK 72                       // bf16 row stride for 64-col tiles
#define OQH 0
#define OQL (128*SRK*2)              // 18432
#define OB0 (2*128*SRK*2)            // 36864
#define KVB (64*SRK*2)               // 9216
#define BUFB (4*KVB)                 // 36864
#define FLASH_SMEM (OB0 + 2*BUFB)    // 110592

__device__ __forceinline__ void flash_issue(uint32_t sb, int buf,
                                            int bh, int k0, int tid) {
    #pragma unroll
    for (int it = 0; it < 8; ++it) {
        int u = tid + it * 256;
        int arr = u >> 9;
        int rem = u & 511;
        int row = rem >> 3;
        int ck = rem & 7;
        const __nv_bfloat16* src;
        size_t gofs;
        if (arr < 2) {
            src = (arr == 0) ? g_kh : g_kl;
            gofs = ((size_t)bh*Tt + k0 + row)*HD + ck*8;
        } else {
            src = (arr == 2) ? g_vth : g_vtl;
            gofs = ((size_t)bh*HD + row)*Tt + k0 + ck*8;
        }
        uint32_t dst = sb + OB0 + buf*BUFB + arr*KVB + (uint32_t)(row*SRK + ck*8)*2;
        cp_async16(dst, src + gofs);
    }
    CP_COMMIT();
}

__global__ __launch_bounds__(256, 2) void flash_mma(const unsigned* __restrict__ amask) {
    extern __shared__ char smf[];
    uint32_t sb = smem_u32(smf);
    int tid = threadIdx.x, wid = tid >> 5, lane = tid & 31;
    int qr = lane >> 2, qc = lane & 3;
    int g = lane >> 3, lr = lane & 7;
    int bh = blockIdx.y;
    int qb = (gridDim.x - 1) - blockIdx.x;   // big tiles first
    int q0 = qb * 128;
    int nkt = qb * 2 + 2;

    // Q tile load (split) — same cp.async group as tile 0
    #pragma unroll
    for (int it = 0; it < 8; ++it) {
        int u = tid + it * 256;
        int arr = u >> 10;
        int rem = u & 1023;
        int row = rem >> 3;
        int ck = rem & 7;
        const __nv_bfloat16* src = arr ? g_ql : g_qh;
        uint32_t dst = sb + (arr ? OQL : OQH) + (uint32_t)(row*SRK + ck*8)*2;
        cp_async16(dst, src + ((size_t)bh*Tt + q0 + row)*HD + ck*8);
    }
    flash_issue(sb, 0, bh, 0, tid);

    uint32_t qaoff = (uint32_t)(((wid*16 + lr + (g & 1)*8) * SRK + (g >> 1)*8) * 2);
    uint32_t bofff[4];
    #pragma unroll
    for (int jp = 0; jp < 4; ++jp)
        bofff[jp] = (uint32_t)(((jp*16 + lr + (g >> 1)*8) * SRK + (g & 1)*8) * 2);

    int r = wid * 16 + qr;                  // q row within tile
    int rowmax = q0 + wid * 16 + 15;
    // gmem mask row base for this thread's two row-octets
    const unsigned* mrow0 = amask + ((size_t)bh*Tt + q0 + r)*Tt + qc*2;
    const unsigned* mrow1 = mrow0 + (size_t)8*Tt;

    float acc[8][4] = {};
    float m0 = -INFINITY, m1 = -INFINITY, l0 = 0.f, l1 = 0.f;

    for (int kt = 0; kt < nkt; ++kt) {
        int buf = kt & 1;
        int k0 = kt * 64;
        if (kt + 1 < nkt) {
            flash_issue(sb, buf ^ 1, bh, (kt+1)*64, tid);
            CP_WAIT(1);
        } else {
            CP_WAIT(0);
        }
        __syncthreads();

        if (k0 <= rowmax) {
            uint32_t kbh = sb + OB0 + buf*BUFB;
            uint32_t kbl = kbh + KVB;
            uint32_t vbh = kbh + 2*KVB;
            uint32_t vbl = kbh + 3*KVB;

            // ---- mask prefetch (gmem -> regs), hidden behind QK MMAs ----
            uint2 km0[8], km1[8];
            #pragma unroll
            for (int j = 0; j < 8; ++j) {
                km0[j] = *(const uint2*)(mrow0 + k0 + j*8);
                km1[j] = *(const uint2*)(mrow1 + k0 + j*8);
            }

            // ---- S = Q K^T (split 3-term) ----
            float s[8][4] = {};
            #pragma unroll
            for (int ks = 0; ks < 4; ++ks) {
                uint32_t ksb = ks * 32;
                uint32_t ah[4], al[4];
                ldsm4(ah, sb + OQH + qaoff + ksb);
                ldsm4(al, sb + OQL + qaoff + ksb);
                #pragma unroll
                for (int jp = 0; jp < 4; ++jp) {
                    uint32_t kh4[4], kl4[4];
                    ldsm4(kh4, kbh + bofff[jp] + ksb);
                    ldsm4(kl4, kbl + bofff[jp] + ksb);
                    #pragma unroll
                    for (int jj = 0; jj < 2; ++jj) {
                        mma16816(s[jp*2+jj], ah, kh4 + jj*2);
                        mma16816(s[jp*2+jj], ah, kl4 + jj*2);
                        mma16816(s[jp*2+jj], al, kh4 + jj*2);
                    }
                }
            }

            // ---- causal mask ----
            int row0 = q0 + r, row1 = row0 + 8;
            #pragma unroll
            for (int j = 0; j < 8; ++j) {
                int cg = k0 + j*8 + qc*2;
                if (cg     > row0) s[j][0] = -INFINITY;
                if (cg + 1 > row0) s[j][1] = -INFINITY;
                if (cg     > row1) s[j][2] = -INFINITY;
                if (cg + 1 > row1) s[j][3] = -INFINITY;
            }

            // ---- online softmax (undropped denominator) ----
            float mx0 = -INFINITY, mx1 = -INFINITY;
            #pragma unroll
            for (int j = 0; j < 8; ++j) {
                mx0 = fmaxf(mx0, fmaxf(s[j][0], s[j][1]));
                mx1 = fmaxf(mx1, fmaxf(s[j][2], s[j][3]));
            }
            mx0 = fmaxf(mx0, __shfl_xor_sync(0xffffffffu, mx0, 1));
            mx0 = fmaxf(mx0, __shfl_xor_sync(0xffffffffu, mx0, 2));
            mx1 = fmaxf(mx1, __shfl_xor_sync(0xffffffffu, mx1, 1));
            mx1 = fmaxf(mx1, __shfl_xor_sync(0xffffffffu, mx1, 2));
            float m0n = fmaxf(m0, mx0), m1n = fmaxf(m1, mx1);
            float a0 = __expf(m0 - m0n), a1 = __expf(m1 - m1n);
            float sum0 = 0.f, sum1 = 0.f;
            #pragma unroll
            for (int j = 0; j < 8; ++j) {
                float p0 = __expf(s[j][0] - m0n); sum0 += p0;
                float p1 = __expf(s[j][1] - m0n); sum0 += p1;
                float p2 = __expf(s[j][2] - m1n); sum1 += p2;
                float p3 = __expf(s[j][3] - m1n); sum1 += p3;
                s[j][0] = km0[j].x ? p0 * KEEP_INV : 0.f;
                s[j][1] = km0[j].y ? p1 * KEEP_INV : 0.f;
                s[j][2] = km1[j].x ? p2 * KEEP_INV : 0.f;
                s[j][3] = km1[j].y ? p3 * KEEP_INV : 0.f;
            }
            sum0 += __shfl_xor_sync(0xffffffffu, sum0, 1);
            sum0 += __shfl_xor_sync(0xffffffffu, sum0, 2);
            sum1 += __shfl_xor_sync(0xffffffffu, sum1, 1);
            sum1 += __shfl_xor_sync(0xffffffffu, sum1, 2);
            l0 = l0 * a0 + sum0;
            l1 = l1 * a1 + sum1;
            m0 = m0n; m1 = m1n;

            // ---- acc scale + P V (split 3-term, P from registers) ----
            #pragma unroll
            for (int j = 0; j < 8; ++j) {
                acc[j][0] *= a0; acc[j][1] *= a0;
                acc[j][2] *= a1; acc[j][3] *= a1;
            }
            #pragma unroll
            for (int s4 = 0; s4 < 4; ++s4) {
                uint32_t ph[4], pl[4];
                split2(s[2*s4][0],   s[2*s4][1],   ph[0], pl[0]);
                split2(s[2*s4][2],   s[2*s4][3],   ph[1], pl[1]);
                split2(s[2*s4+1][0], s[2*s4+1][1], ph[2], pl[2]);
                split2(s[2*s4+1][2], s[2*s4+1][3], ph[3], pl[3]);
                uint32_t ksb = s4 * 32;
                #pragma unroll
                for (int jp = 0; jp < 4; ++jp) {
                    uint32_t vh4[4], vl4[4];
                    ldsm4(vh4, vbh + bofff[jp] + ksb);
                    ldsm4(vl4, vbl + bofff[jp] + ksb);
                    #pragma unroll
                    for (int jj = 0; jj < 2; ++jj) {
                        mma16816(acc[jp*2+jj], ph, vh4 + jj*2);
                        mma16816(acc[jp*2+jj], ph, vl4 + jj*2);
                        mma16816(acc[jp*2+jj], pl, vh4 + jj*2);
                    }
                }
            }
        }
        __syncthreads();
    }

    // ---- epilogue: y = acc / l, write split bf16 [tok][C] ----
    int b = bh >> 4, h = bh & 15;
    float inv0 = 1.f / l0, inv1 = 1.f / l1;
    size_t tok0 = (size_t)b*Tt + q0 + r;
    size_t tok1 = tok0 + 8;
    #pragma unroll
    for (int j = 0; j < 8; ++j) {
        int col = h*HD + j*8 + qc*2;
        uint32_t hi, lo;
        split2(acc[j][0]*inv0, acc[j][1]*inv0, hi, lo);
        *(uint32_t*)&g_yh[tok0*Cc + col] = hi;
        *(uint32_t*)&g_yl[tok0*Cc + col] = lo;
        split2(acc[j][2]*inv1, acc[j][3]*inv1, hi, lo);
        *(uint32_t*)&g_yh[tok1*Cc + col] = hi;
        *(uint32_t*)&g_yl[tok1*Cc + col] = lo;
    }
}

// ---------------------------------------------------------------------------
extern "C" void kernel_launch(void* const* d_in, const int* in_sizes, int n_in,
                              void* d_out, int out_size) {
    const float* x     = (const float*)d_in[0];
    const float* Wqkv  = (const float*)d_in[1];
    const float* bqkv  = (const float*)d_in[2];
    const float* Wproj = (const float*)d_in[3];
    const float* bproj = (const float*)d_in[4];
    const unsigned* amask = (const unsigned*)d_in[5];
    const unsigned* rmask = (const unsigned*)d_in[6];
    float* out = (float*)d_out;

    cudaFuncSetAttribute(gemm_mma<0>, cudaFuncAttributeMaxDynamicSharedMemorySize, GEMM_SMEM);
    cudaFuncSetAttribute(gemm_mma<1>, cudaFuncAttributeMaxDynamicSharedMemorySize, GEMM_SMEM);
    cudaFuncSetAttribute(flash_mma, cudaFuncAttributeMaxDynamicSharedMemorySize, FLASH_SMEM);

    __nv_bfloat16 *xh, *xl, *wqh, *wql, *wph, *wpl, *yh, *yl;
    cudaGetSymbolAddress((void**)&xh,  g_xh);  cudaGetSymbolAddress((void**)&xl,  g_xl);
    cudaGetSymbolAddress((void**)&wqh, g_wqh); cudaGetSymbolAddress((void**)&wql, g_wql);
    cudaGetSymbolAddress((void**)&wph, g_wph); cudaGetSymbolAddress((void**)&wpl, g_wpl);
    cudaGetSymbolAddress((void**)&yh,  g_yh);  cudaGetSymbolAddress((void**)&yl,  g_yl);

    cvt_split<<<(NTOK*Cc/4 + 255)/256, 256>>>((const float4*)x, (__nv_bfloat162*)xh, (__nv_bfloat162*)xl, NTOK*Cc/4);
    cvt_split_T<<<dim3(C3/32, Cc/32), dim3(32,8)>>>(Wqkv, wqh, wql, Cc, C3);
    cvt_split_T<<<dim3(Cc/32, Cc/32), dim3(32,8)>>>(Wproj, wph, wpl, Cc, Cc);

    gemm_mma<0><<<dim3(C3/128, NTOK/128), 256, GEMM_SMEM>>>(xh, xl, wqh, wql, bqkv, nullptr, nullptr, Cc);

    flash_mma<<<dim3(Tt/128, Bsz*Hh), 256, FLASH_SMEM>>>(amask);

    gemm_mma<1><<<dim3(Cc/128, NTOK/128), 256, GEMM_SMEM>>>(yh, yl, wph, wpl, bproj, rmask, out, Cc);
}